// round 1
// baseline (speedup 1.0000x reference)
#include <cuda_runtime.h>
#include <math.h>

// ---------------------------------------------------------------------------
// TV denoiser (Chambolle-Pock primal-dual with over-relaxation), fused.
//   x  = (x2 - TAU*adj(u2) + TAU*y) / (1+TAU)
//   v  = u2 + SIGMA * nabla(2x - x2)
//   u  = v / max(|v|/THS, 1)
//   x2' = x2 + RHO*(x - x2);  u2' = u2 + RHO*(u - u2)
// Early exit when it>=3 && ||x2-x2'|| / ||x2'+1e-12|| < 1e-5.
// ---------------------------------------------------------------------------

#define BATCH 8
#define HH 512
#define WW 512
#define NTOT (BATCH*HH*WW)

#define TX 32
#define TY 8
#define NBLK ((WW/TX)*(HH/TY)*BATCH)   // 16*64*8 = 8192

#define TAUc     0.01f
#define INV1PTAU (1.0f/1.01f)
#define SIGMAc   12.5f                 // 1/TAU/8
#define RHOc     1.99f
#define THSc     0.1f
#define CRITc    1e-5f
#define NITERc   40

// Ping-pong state in device globals (no allocations allowed).
__device__ float g_x [2][NTOT];
__device__ float g_u0[2][NTOT];
__device__ float g_u1[2][NTOT];
__device__ float g_pnum[NBLK];
__device__ float g_pden[NBLK];
__device__ int          g_converged;
__device__ int          g_executed;
__device__ unsigned int g_counter;

__global__ void tv_init_kernel(const float* __restrict__ y) {
    int i = blockIdx.x * blockDim.x + threadIdx.x;
    int stride = gridDim.x * blockDim.x;
    for (; i < NTOT; i += stride) {
        g_x [0][i] = y[i];
        g_u0[0][i] = 0.f;
        g_u1[0][i] = 0.f;
    }
    if (blockIdx.x == 0 && threadIdx.x == 0) {
        g_converged = 0;
        g_executed  = 0;
        g_counter   = 0u;
    }
}

__global__ __launch_bounds__(TX*TY)
void tv_step_kernel(const float* __restrict__ y, int t) {
    if (g_converged) return;   // uniform across all threads

    const int p = t & 1;
    const float* __restrict__ xin  = g_x [p];
    float*       __restrict__ xout = g_x [p ^ 1];
    const float* __restrict__ u0in = g_u0[p];
    const float* __restrict__ u1in = g_u1[p];
    float*       __restrict__ u0out = g_u0[p ^ 1];
    float*       __restrict__ u1out = g_u1[p ^ 1];

    __shared__ float zsh[TY + 1][TX + 1];   // 9 x 33, odd row stride -> no conflicts

    const int c0   = blockIdx.x * TX;
    const int r0   = blockIdx.y * TY;
    const int base = blockIdx.z * (HH * WW);
    const int tid  = threadIdx.y * TX + threadIdx.x;

    // -- compute z = 2x - x2 for the extended (TY+1)x(TX+1) tile ------------
    for (int idx = tid; idx < (TY + 1) * (TX + 1); idx += TX * TY) {
        int ly = idx / (TX + 1);
        int lx = idx - ly * (TX + 1);
        int gi = r0 + ly, gj = c0 + lx;
        float zv = 0.f;
        if (gi < HH && gj < WW) {
            int g = base + gi * WW + gj;
            float a = 0.f;                          // nabla2_adjoint(u2)(gi,gj)
            if (gi < HH - 1) a -= u0in[g];
            if (gi > 0)      a += u0in[g - WW];
            if (gj < WW - 1) a -= u1in[g];
            if (gj > 0)      a += u1in[g - 1];
            float x2v = xin[g];
            float xv  = (x2v + TAUc * (y[g] - a)) * INV1PTAU;
            zv = 2.f * xv - x2v;
        }
        zsh[ly][lx] = zv;
    }
    __syncthreads();

    // -- per-pixel update ----------------------------------------------------
    const int i = r0 + threadIdx.y;
    const int j = c0 + threadIdx.x;
    const int g = base + i * WW + j;

    float z  = zsh[threadIdx.y][threadIdx.x];
    float dh = (i < HH - 1) ? (zsh[threadIdx.y + 1][threadIdx.x] - z) : 0.f;
    float dw = (j < WW - 1) ? (zsh[threadIdx.y][threadIdx.x + 1] - z) : 0.f;

    float u0v = u0in[g], u1v = u1in[g];
    float v0 = u0v + SIGMAc * dh;
    float v1 = u1v + SIGMAc * dw;
    float mag = sqrtf(v0 * v0 + v1 * v1);
    float s = (mag > THSc) ? (THSc / mag) : 1.f;

    float x2v = xin[g];
    float xv  = 0.5f * (z + x2v);
    float xn  = x2v + RHOc * (xv - x2v);
    float u0n = u0v + RHOc * (v0 * s - u0v);
    float u1n = u1v + RHOc * (v1 * s - u1v);

    xout[g]  = xn;
    u0out[g] = u0n;
    u1out[g] = u1n;

    // -- convergence statistics (deterministic last-block reduction) ---------
    float d   = x2v - xn;
    float num = d * d;
    float dd  = xn + 1e-12f;
    float den = dd * dd;

    #pragma unroll
    for (int o = 16; o; o >>= 1) {
        num += __shfl_down_sync(0xffffffffu, num, o);
        den += __shfl_down_sync(0xffffffffu, den, o);
    }
    __shared__ float snum[TX * TY / 32], sden[TX * TY / 32];
    const int warp = tid >> 5, lane = tid & 31;
    if (lane == 0) { snum[warp] = num; sden[warp] = den; }
    __syncthreads();

    const int blin = blockIdx.x + gridDim.x * (blockIdx.y + gridDim.y * blockIdx.z);
    if (tid == 0) {
        float n2 = 0.f, d2 = 0.f;
        #pragma unroll
        for (int w = 0; w < TX * TY / 32; w++) { n2 += snum[w]; d2 += sden[w]; }
        g_pnum[blin] = n2;
        g_pden[blin] = d2;
    }

    __shared__ unsigned int s_ticket;
    if (tid == 0) {
        __threadfence();
        s_ticket = atomicInc(&g_counter, 0xffffffffu);
    }
    __syncthreads();

    if (s_ticket == NBLK - 1) {   // last block: fixed-order reduce -> deterministic
        float n2 = 0.f, d2 = 0.f;
        for (int k = tid; k < NBLK; k += TX * TY) { n2 += g_pnum[k]; d2 += g_pden[k]; }
        #pragma unroll
        for (int o = 16; o; o >>= 1) {
            n2 += __shfl_down_sync(0xffffffffu, n2, o);
            d2 += __shfl_down_sync(0xffffffffu, d2, o);
        }
        if (lane == 0) { snum[warp] = n2; sden[warp] = d2; }
        __syncthreads();
        if (tid == 0) {
            float N = 0.f, D = 0.f;
            #pragma unroll
            for (int w = 0; w < TX * TY / 32; w++) { N += snum[w]; D += sden[w]; }
            float rel = sqrtf(N) / sqrtf(D);
            int e = g_executed + 1;
            g_executed = e;
            if (e >= 3 && rel < CRITc) g_converged = 1;
            g_counter = 0u;
        }
    }
}

__global__ void tv_final_kernel(float* __restrict__ out) {
    const int parity = g_executed & 1;
    const float* __restrict__ src = g_x[parity];
    int i = blockIdx.x * blockDim.x + threadIdx.x;
    int stride = gridDim.x * blockDim.x;
    for (; i < NTOT; i += stride) out[i] = src[i];
}

extern "C" void kernel_launch(void* const* d_in, const int* in_sizes, int n_in,
                              void* d_out, int out_size) {
    const float* y = (const float*)d_in[0];
    float* out = (float*)d_out;

    tv_init_kernel<<<512, 256>>>(y);

    dim3 blk(TX, TY);
    dim3 grd(WW / TX, HH / TY, BATCH);
    for (int t = 0; t < NITERc; t++) {
        tv_step_kernel<<<grd, blk>>>(y, t);
    }

    tv_final_kernel<<<512, 256>>>(out);
}

// round 2
// speedup vs baseline: 2.1025x; 2.1025x over previous
#include <cuda_runtime.h>

// Persistent-kernel TV denoiser (Chambolle-Pock, RHO-relaxed), single launch.
// 128 blocks x 512 threads; each thread marches a 16-row column segment.

#define BATCH 8
#define HH 512
#define WW 512
#define IMG (HH*WW)
#define NTOT (BATCH*IMG)
#define ROWS 16
#define STRIPES_PER_IMG (HH/ROWS)          // 32
#define NSTRIPES (BATCH*STRIPES_PER_IMG)   // 256
#define NBLK 128
#define NTHR 512
#define NWARP (NTHR/32)

#define TAUc     0.01f
#define INV1PTAU (1.0f/1.01f)
#define SIGMAc   12.5f
#define RHOc     1.99f
#define HRHOc    0.995f      /* RHO/2 */
#define THSc     0.1f
#define THS2c    0.01f       /* THS^2 */
#define CRITc    1e-5f
#define NITERc   40

__device__ float g_x [2][NTOT];
__device__ float g_u0[2][NTOT];
__device__ float g_u1[2][NTOT];
__device__ float g_pnum[2][NBLK];
__device__ float g_pden[2][NBLK];
__device__ unsigned int          g_count = 0;
__device__ volatile unsigned int g_gen   = 0;

__device__ __forceinline__ void grid_barrier()
{
    __threadfence();            // order my writes (CCTL.IVALL on gpu scope)
    __syncthreads();
    if (threadIdx.x == 0) {
        unsigned int gen = g_gen;
        if (atomicInc(&g_count, NBLK - 1u) == NBLK - 1u) {
            g_gen = gen + 1u;                 // release
        } else {
            while (g_gen == gen) __nanosleep(64);
        }
    }
    __syncthreads();
    __threadfence();            // flush L1 before reading other SMs' writes
}

// z = 2x - x2 at (i, j); u0_prev = u0[i-1][j] (0 when i==0).
__device__ __forceinline__ void rowz(
    const float* __restrict__ xin, const float* __restrict__ u0in,
    const float* __restrict__ u1in, const float* __restrict__ yv,
    int g, int i, int j, float u0_prev,
    float& u0c, float& u1c, float& x2c, float& zc)
{
    u0c = u0in[g];
    u1c = u1in[g];
    float u1m = (j > 0) ? u1in[g - 1] : 0.f;
    x2c = xin[g];
    float yy = yv[g];
    float a = u0_prev + u1m;
    if (i < HH - 1) a -= u0c;
    if (j < WW - 1) a -= u1c;
    float xv = (x2c + TAUc * (yy - a)) * INV1PTAU;
    zc = 2.f * xv - x2c;
}

// Standalone z at (i, j) given u1[i][j-1]; used for the lane-31 dw fixup.
__device__ __forceinline__ float z_at(
    const float* __restrict__ xin, const float* __restrict__ u0in,
    const float* __restrict__ u1in, const float* __restrict__ yv,
    int g, int i, int j, float u1left)
{
    float u0c = u0in[g];
    float u0p = (i > 0) ? u0in[g - WW] : 0.f;
    float u1c = u1in[g];
    float x2c = xin[g];
    float yy  = yv[g];
    float a = u0p + u1left;
    if (i < HH - 1) a -= u0c;
    if (j < WW - 1) a -= u1c;
    float xv = (x2c + TAUc * (yy - a)) * INV1PTAU;
    return 2.f * xv - x2c;
}

__global__ void __launch_bounds__(NTHR, 2)
tv_persistent(const float* __restrict__ yv, float* __restrict__ out)
{
    const int j    = threadIdx.x;          // column within the image row
    const int lane = j & 31;
    const int wid  = j >> 5;
    const int blk  = blockIdx.x;

    __shared__ float snum[NWARP], sden[NWARP];
    __shared__ float sdec;

    // ---- init: x2 = y, u = 0 ----
    for (int st = blk; st < NSTRIPES; st += NBLK) {
        const int b = st / STRIPES_PER_IMG;
        const int s = st % STRIPES_PER_IMG;
        int g = b * IMG + (s * ROWS) * WW + j;
        #pragma unroll
        for (int r = 0; r < ROWS; r++, g += WW) {
            g_x [0][g] = yv[g];
            g_u0[0][g] = 0.f;
            g_u1[0][g] = 0.f;
        }
    }
    grid_barrier();

    int executed = NITERc;

    for (int t = 0; t < NITERc; t++) {
        const int p = t & 1;
        const float* __restrict__ xin  = g_x [p];
        const float* __restrict__ u0in = g_u0[p];
        const float* __restrict__ u1in = g_u1[p];
        float* __restrict__ xout  = g_x [p ^ 1];
        float* __restrict__ u0out = g_u0[p ^ 1];
        float* __restrict__ u1out = g_u1[p ^ 1];

        float num = 0.f, den = 0.f;

        for (int st = blk; st < NSTRIPES; st += NBLK) {
            const int b  = st / STRIPES_PER_IMG;
            const int s  = st % STRIPES_PER_IMG;
            const int i0 = s * ROWS;
            int g = b * IMG + i0 * WW + j;

            float u0pm = (i0 > 0) ? u0in[g - WW] : 0.f;
            float u0c, u1c, x2c, zc;
            rowz(xin, u0in, u1in, yv, g, i0, j, u0pm, u0c, u1c, x2c, zc);

            #pragma unroll 4
            for (int r = 0; r < ROWS; r++) {
                const int i = i0 + r;
                float u0N = 0.f, u1N = 0.f, x2N = 0.f, zN = 0.f;
                if (i + 1 < HH)
                    rowz(xin, u0in, u1in, yv, g + WW, i + 1, j, u0c,
                         u0N, u1N, x2N, zN);

                float zr = __shfl_down_sync(0xffffffffu, zc, 1);
                if (lane == 31 && j < WW - 1)
                    zr = z_at(xin, u0in, u1in, yv, g + 1, i, j + 1, u1c);

                float dh = (i < HH - 1) ? (zN - zc) : 0.f;
                float dw = (j < WW - 1) ? (zr - zc) : 0.f;

                float v0 = fmaf(SIGMAc, dh, u0c);
                float v1 = fmaf(SIGMAc, dw, u1c);
                float m2 = v0 * v0 + v1 * v1;
                float sc = (m2 > THS2c) ? (THSc * rsqrtf(m2)) : 1.f;

                float xn  = fmaf(HRHOc, zc - x2c, x2c);
                float u0n = fmaf(RHOc, fmaf(v0, sc, -u0c), u0c);
                float u1n = fmaf(RHOc, fmaf(v1, sc, -u1c), u1c);

                xout[g]  = xn;
                u0out[g] = u0n;
                u1out[g] = u1n;

                float d  = xn - x2c;
                num = fmaf(d, d, num);
                float dd = xn + 1e-12f;
                den = fmaf(dd, dd, den);

                zc = zN; u0c = u0N; u1c = u1N; x2c = x2N;
                g += WW;
            }
        }

        // deterministic block reduction
        #pragma unroll
        for (int o = 16; o; o >>= 1) {
            num += __shfl_down_sync(0xffffffffu, num, o);
            den += __shfl_down_sync(0xffffffffu, den, o);
        }
        if (lane == 0) { snum[wid] = num; sden[wid] = den; }
        __syncthreads();
        if (j == 0) {
            float n2 = 0.f, d2 = 0.f;
            #pragma unroll
            for (int w = 0; w < NWARP; w++) { n2 += snum[w]; d2 += sden[w]; }
            g_pnum[p][blk] = n2;
            g_pden[p][blk] = d2;
        }

        grid_barrier();

        // every block computes the identical rel (fixed order -> deterministic)
        if (j == 0) {
            float N = 0.f, D = 0.f;
            for (int k = 0; k < NBLK; k++) { N += g_pnum[p][k]; D += g_pden[p][k]; }
            sdec = sqrtf(N) / sqrtf(D);
        }
        __syncthreads();
        if (t + 1 >= 3 && sdec < CRITc) { executed = t + 1; break; }
    }

    // ---- write output from the buffer holding the final state ----
    const float* __restrict__ src = g_x[executed & 1];
    for (int st = blk; st < NSTRIPES; st += NBLK) {
        const int b = st / STRIPES_PER_IMG;
        const int s = st % STRIPES_PER_IMG;
        int g = b * IMG + (s * ROWS) * WW + j;
        #pragma unroll
        for (int r = 0; r < ROWS; r++, g += WW)
            out[g] = src[g];
    }
}

extern "C" void kernel_launch(void* const* d_in, const int* in_sizes, int n_in,
                              void* d_out, int out_size) {
    const float* y = (const float*)d_in[0];
    float* out = (float*)d_out;
    tv_persistent<<<NBLK, NTHR>>>(y, out);
}

// round 3
// speedup vs baseline: 3.5683x; 1.6972x over previous
#include <cuda_runtime.h>

// Persistent-kernel TV denoiser (Chambolle-Pock, RHO-relaxed), single launch.
// 512 blocks x 256 threads; each thread owns 2 adjacent columns (float2) and
// marches an 8-row stripe. One grid barrier per iteration.

#define BATCH 8
#define HH 512
#define WW 512
#define IMG (HH*WW)
#define NTOT (BATCH*IMG)
#define ROWS 8
#define SPI (HH/ROWS)            // 64 stripes per image
#define NBLK (BATCH*SPI)         // 512 blocks, one stripe each
#define NTHR 256
#define NWARP (NTHR/32)

#define TAUc     0.01f
#define INV1PTAU (1.0f/1.01f)
#define SIGMAc   12.5f
#define RHOc     1.99f
#define HRHOc    0.995f          /* RHO/2 */
#define THSc     0.1f
#define THS2c    0.01f           /* THS^2 */
#define CRITc    1e-5f
#define NITERc   40

__device__ float g_x [2][NTOT];
__device__ float g_u0[2][NTOT];
__device__ float g_u1[2][NTOT];
__device__ float g_pnum[2][NBLK];
__device__ float g_pden[2][NBLK];
__device__ unsigned int          g_count = 0;
__device__ volatile unsigned int g_gen   = 0;

__device__ __forceinline__ void grid_barrier()
{
    __threadfence();
    __syncthreads();
    if (threadIdx.x == 0) {
        unsigned int gen = g_gen;
        if (atomicInc(&g_count, NBLK - 1u) == NBLK - 1u) {
            g_gen = gen + 1u;
        } else {
            while (g_gen == gen) __nanosleep(64);
        }
    }
    __syncthreads();
    __threadfence();
}

// Compute z = 2x - x2 for this thread's column pair at row i, plus the lane-31
// fixup column (c0+2). u0prev / u0fixprev are the previous-row u0 values
// (register-carried). Contains warp shuffles: call only with block-uniform i.
__device__ __forceinline__ void row_pair(
    const float* __restrict__ xin, const float* __restrict__ u0in,
    const float* __restrict__ u1in, const float* __restrict__ yv,
    int g, int i, int tid, int lane, bool cfixOK,
    float2 u0prev, float u0fixprev,
    float2& u0c, float2& u1c, float2& x2c,
    float& z0, float& z1, float& zf, float& u0fc)
{
    u0c = *(const float2*)(u0in + g);
    u1c = *(const float2*)(u1in + g);
    x2c = *(const float2*)(xin  + g);
    float2 yc = *(const float2*)(yv + g);

    float u1left = __shfl_up_sync(0xffffffffu, u1c.y, 1);
    if (lane == 0) u1left = (tid > 0) ? u1in[g - 1] : 0.f;

    const bool nl = (i < HH - 1);
    float u0cx = nl ? u0c.x : 0.f;
    float u0cy = nl ? u0c.y : 0.f;
    float u1cy = (tid == NTHR - 1) ? 0.f : u1c.y;   // col 511 has no right diff

    float a0 = u0prev.x + u1left - u0cx - u1c.x;
    float a1 = u0prev.y + u1c.x  - u0cy - u1cy;

    float x0 = fmaf(TAUc, yc.x - a0, x2c.x) * INV1PTAU;
    float x1 = fmaf(TAUc, yc.y - a1, x2c.y) * INV1PTAU;
    z0 = 2.f * x0 - x2c.x;
    z1 = 2.f * x1 - x2c.y;

    zf = 0.f; u0fc = 0.f;
    if (cfixOK) {                       // lane 31 (except tid 255): column c0+2
        float u0f = u0in[g + 2];
        float u1f = u1in[g + 2];
        float x2f = xin [g + 2];
        float yf  = yv  [g + 2];
        float u0fx = nl ? u0f : 0.f;
        float af = u0fixprev + u1c.y - u0fx - u1f;   // cfix <= 448 < 511
        float xf = fmaf(TAUc, yf - af, x2f) * INV1PTAU;
        zf = 2.f * xf - x2f;
        u0fc = u0f;
    }
}

__global__ void __launch_bounds__(NTHR, 4)
tv_persistent(const float* __restrict__ yv, float* __restrict__ out)
{
    const int tid  = threadIdx.x;
    const int lane = tid & 31;
    const int wid  = tid >> 5;
    const int blk  = blockIdx.x;
    const bool cfixOK = (lane == 31) && (tid != NTHR - 1);

    const int b  = blk >> 6;           // image
    const int s  = blk & 63;           // stripe within image
    const int i0 = s * ROWS;
    const int g0 = b * IMG + i0 * WW + 2 * tid;

    __shared__ float snum[NWARP], sden[NWARP];
    __shared__ float sdec;

    // ---- init own stripe: x2 = y, u = 0 ----
    {
        int gg = g0;
        const float2 zz = make_float2(0.f, 0.f);
        #pragma unroll
        for (int r = 0; r < ROWS; r++, gg += WW) {
            *(float2*)(g_x [0] + gg) = *(const float2*)(yv + gg);
            *(float2*)(g_u0[0] + gg) = zz;
            *(float2*)(g_u1[0] + gg) = zz;
        }
    }
    grid_barrier();

    int executed = NITERc;

    for (int t = 0; t < NITERc; t++) {
        const int p = t & 1;
        const float* __restrict__ xin  = g_x [p];
        const float* __restrict__ u0in = g_u0[p];
        const float* __restrict__ u1in = g_u1[p];
        float* __restrict__ xout  = g_x [p ^ 1];
        float* __restrict__ u0out = g_u0[p ^ 1];
        float* __restrict__ u1out = g_u1[p ^ 1];

        // prologue: row i0
        float2 u0prev = (i0 > 0) ? *(const float2*)(u0in + g0 - WW)
                                 : make_float2(0.f, 0.f);
        float u0fixprev = (cfixOK && i0 > 0) ? u0in[g0 + 2 - WW] : 0.f;

        float2 u0c, u1c, x2c;
        float zc0, zc1, zfc, u0fc;
        row_pair(xin, u0in, u1in, yv, g0, i0, tid, lane, cfixOK,
                 u0prev, u0fixprev, u0c, u1c, x2c, zc0, zc1, zfc, u0fc);

        float num = 0.f, den = 0.f;
        int g = g0;

        #pragma unroll
        for (int r = 0; r < ROWS; r++) {
            const int i = i0 + r;

            float2 u0N = make_float2(0.f, 0.f), u1N = u0N, x2N = u0N;
            float zN0 = 0.f, zN1 = 0.f, zfN = 0.f, u0fN = 0.f;
            if (i + 1 < HH)     // block-uniform
                row_pair(xin, u0in, u1in, yv, g + WW, i + 1, tid, lane, cfixOK,
                         u0c, u0fc, u0N, u1N, x2N, zN0, zN1, zfN, u0fN);

            float dw0 = zc1 - zc0;
            float zsh = __shfl_down_sync(0xffffffffu, zc0, 1);
            float zr1 = (lane == 31) ? zfc : zsh;
            float dw1 = (tid == NTHR - 1) ? 0.f : (zr1 - zc1);

            const bool nl = (i < HH - 1);
            float dh0 = nl ? (zN0 - zc0) : 0.f;
            float dh1 = nl ? (zN1 - zc1) : 0.f;

            float v00 = fmaf(SIGMAc, dh0, u0c.x);
            float v10 = fmaf(SIGMAc, dw0, u1c.x);
            float v01 = fmaf(SIGMAc, dh1, u0c.y);
            float v11 = fmaf(SIGMAc, dw1, u1c.y);

            float m20 = fmaf(v00, v00, v10 * v10);
            float m21 = fmaf(v01, v01, v11 * v11);
            float sc0 = (m20 > THS2c) ? (THSc * rsqrtf(m20)) : 1.f;
            float sc1 = (m21 > THS2c) ? (THSc * rsqrtf(m21)) : 1.f;

            float2 xn, u0n, u1n;
            xn.x  = fmaf(HRHOc, zc0 - x2c.x, x2c.x);
            xn.y  = fmaf(HRHOc, zc1 - x2c.y, x2c.y);
            u0n.x = fmaf(RHOc, fmaf(v00, sc0, -u0c.x), u0c.x);
            u0n.y = fmaf(RHOc, fmaf(v01, sc1, -u0c.y), u0c.y);
            u1n.x = fmaf(RHOc, fmaf(v10, sc0, -u1c.x), u1c.x);
            u1n.y = fmaf(RHOc, fmaf(v11, sc1, -u1c.y), u1c.y);

            *(float2*)(xout  + g) = xn;
            *(float2*)(u0out + g) = u0n;
            *(float2*)(u1out + g) = u1n;

            float d0 = xn.x - x2c.x, d1 = xn.y - x2c.y;
            num = fmaf(d0, d0, num);  num = fmaf(d1, d1, num);
            float e0 = xn.x + 1e-12f, e1 = xn.y + 1e-12f;
            den = fmaf(e0, e0, den);  den = fmaf(e1, e1, den);

            u0c = u0N; u1c = u1N; x2c = x2N;
            zc0 = zN0; zc1 = zN1; zfc = zfN; u0fc = u0fN;
            g += WW;
        }

        // convergence path only matters from t >= 2 (decision needs it >= 3)
        if (t >= 2) {
            #pragma unroll
            for (int o = 16; o; o >>= 1) {
                num += __shfl_down_sync(0xffffffffu, num, o);
                den += __shfl_down_sync(0xffffffffu, den, o);
            }
            if (lane == 0) { snum[wid] = num; sden[wid] = den; }
            __syncthreads();
            if (tid == 0) {
                float n2 = 0.f, d2 = 0.f;
                #pragma unroll
                for (int w = 0; w < NWARP; w++) { n2 += snum[w]; d2 += sden[w]; }
                g_pnum[p][blk] = n2;
                g_pden[p][blk] = d2;
            }
        }

        grid_barrier();

        if (t >= 2) {
            // every block redundantly reduces the 512 partials in an identical
            // fixed order -> identical float result -> identical decision.
            float n2 = g_pnum[p][tid] + g_pnum[p][tid + NTHR];
            float d2 = g_pden[p][tid] + g_pden[p][tid + NTHR];
            #pragma unroll
            for (int o = 16; o; o >>= 1) {
                n2 += __shfl_down_sync(0xffffffffu, n2, o);
                d2 += __shfl_down_sync(0xffffffffu, d2, o);
            }
            if (lane == 0) { snum[wid] = n2; sden[wid] = d2; }
            __syncthreads();
            if (tid == 0) {
                float N = 0.f, D = 0.f;
                #pragma unroll
                for (int w = 0; w < NWARP; w++) { N += snum[w]; D += sden[w]; }
                sdec = sqrtf(N) / sqrtf(D);
            }
            __syncthreads();
            if (sdec < CRITc) { executed = t + 1; break; }
            __syncthreads();   // protect snum/sden reuse next iteration
        }
    }

    // ---- write own stripe from the buffer holding the final state ----
    const float* __restrict__ src = g_x[executed & 1];
    int gg = g0;
    #pragma unroll
    for (int r = 0; r < ROWS; r++, gg += WW)
        *(float2*)(out + gg) = *(const float2*)(src + gg);
}

extern "C" void kernel_launch(void* const* d_in, const int* in_sizes, int n_in,
                              void* d_out, int out_size) {
    const float* y = (const float*)d_in[0];
    float* out = (float*)d_out;
    tv_persistent<<<NBLK, NTHR>>>(y, out);
}